// round 5
// baseline (speedup 1.0000x reference)
#include <cuda_runtime.h>
#include <cstdint>
#include <math.h>

// CTC batch cost (TF/Keras: blank = last class, lp = log(p + 1e-7)).
// Forward algorithm in EXTENDED-RANGE arithmetic: each state alpha[s] is
// (mantissa in [0.5,1) or 0, int exponent; value = m * 2^e). This gives
// unbounded per-state dynamic range (needed: cross-state ratios reach e^300+)
// with pure ALU/FMA math — no logs/exps in the hot loop.
// One CTA per batch element; thread s owns state s (S = 201).
// Probability rows streamed via cp.async ring (8 slots, 4 groups in flight).

namespace {
constexpr int kB = 256;
constexpr int kT = 1024;
constexpr int kC = 128;
constexpr int kU = 100;
constexpr int kS = 2 * kU + 1;   // 201
constexpr int kBlank = kC - 1;   // 127
constexpr float kEps = 1e-7f;
constexpr int RING = 8;
constexpr int DEPTH = 4;
constexpr int SENT = -(1 << 30); // exponent sentinel for value == 0
}

__device__ __forceinline__ void cp_async4(void* smem, const void* gmem) {
    unsigned s = (unsigned)__cvta_generic_to_shared(smem);
    asm volatile("cp.async.ca.shared.global [%0], [%1], 4;" :: "r"(s), "l"(gmem));
}
__device__ __forceinline__ void cp_commit() {
    asm volatile("cp.async.commit_group;");
}
__device__ __forceinline__ void cp_wait3() {
    asm volatile("cp.async.wait_group 3;");
}

// 2^d for int d <= 0; exact +0.0f for d <= -127. Pure ALU.
__device__ __forceinline__ float exp2neg(int d) {
    d = max(d, -127);
    return __int_as_float((127 + d) << 23);
}

__global__ __launch_bounds__(256, 2)
void ctc_kernel(const float* __restrict__ y_pred,
                const int* __restrict__ y_true,
                const int* __restrict__ label_len,
                float* __restrict__ out)
{
    __shared__ float prow[RING][kC];   // prob rows (raw; +eps at consume)
    __shared__ float am[2][kS + 2];    // mantissas, 2 zero pads on the left
    __shared__ int   ae[2][kS + 2];    // exponents (SENT for zero)

    const int b   = blockIdx.x;
    const int tid = threadIdx.x;
    const float* __restrict__ base = y_pred + (size_t)b * kT * kC;

    // Per-state class index + skip-transition flag.
    int cls = kBlank;
    bool skip = false;
    if (tid < kS && (tid & 1)) {
        cls = y_true[b * kU + (tid >> 1)];
        if (tid >= 3) skip = (cls != y_true[b * kU + (tid >> 1) - 1]);
    }

    if (tid < 2) {
        am[0][tid] = 0.f; am[1][tid] = 0.f;
        ae[0][tid] = SENT; ae[1][tid] = SENT;
    }

    // Prologue: issue rows 0..3, one commit group each.
    #pragma unroll
    for (int r = 0; r < DEPTH; ++r) {
        if (tid < kC) cp_async4(&prow[r][tid], base + r * kC + tid);
        cp_commit();
    }

    cp_wait3();          // row 0 landed (per-thread)
    __syncthreads();     // row 0 + pads visible block-wide

    // t = 0: only states 0 (blank) and 1 (first label) reachable.
    if (tid < kS) {
        float mn = 0.f; int en = SENT;
        if (tid < 2) {
            float q = prow[0][cls] + kEps;     // cls==kBlank for tid 0
            int vi = __float_as_int(q);
            int vexp = (vi >> 23) & 255;
            mn = __int_as_float((vi & 0x807FFFFF) | (126 << 23));
            en = vexp - 126;
        }
        am[0][tid + 2] = mn;
        ae[0][tid + 2] = en;
    }
    if (tid < kC) cp_async4(&prow[DEPTH & (RING - 1)][tid], base + DEPTH * kC + tid);
    cp_commit();

    for (int t = 1; t < kT; ++t) {
        cp_wait3();          // row t landed
        __syncthreads();     // row t + alpha_{t-1} visible

        // Prefetch row t+4 (slot last read 4 barriers ago).
        const int rowi = t + DEPTH;
        if (rowi < kT && tid < kC)
            cp_async4(&prow[rowi & (RING - 1)][tid], base + (size_t)rowi * kC + tid);
        cp_commit();         // uniform group count

        const float* __restrict__ amo = am[(t + 1) & 1];
        const int*   __restrict__ aeo = ae[(t + 1) & 1];
        if (tid < kS) {
            float m0 = amo[tid + 2]; int e0 = aeo[tid + 2];
            float m1 = amo[tid + 1]; int e1 = aeo[tid + 1];
            float m2 = 0.f;          int e2 = SENT;
            if (skip) { m2 = amo[tid]; e2 = aeo[tid]; }

            int emax = max(e0, max(e1, e2));
            float sum = m0 * exp2neg(e0 - emax);
            sum = fmaf(m1, exp2neg(e1 - emax), sum);
            sum = fmaf(m2, exp2neg(e2 - emax), sum);

            float q = prow[t & (RING - 1)][cls] + kEps;
            float val = sum * q;     // in [5e-8, 3.5) if nonzero -> always normal

            float mn = 0.f; int en = SENT;
            if (val > 0.f) {
                int vi = __float_as_int(val);
                int vexp = (vi >> 23) & 255;
                mn = __int_as_float((vi & 0x807FFFFF) | (126 << 23));
                en = emax + (vexp - 126);
            }
            am[t & 1][tid + 2] = mn;
            ae[t & 1][tid + 2] = en;
        }
    }

    __syncthreads();     // make t = T-1 writes visible to thread 0
    if (tid == 0) {
        const int L = label_len[b];
        const int end = 2 * L;                 // in [2, 200]
        const float* mF = am[(kT - 1) & 1];
        const int*   eF = ae[(kT - 1) & 1];
        float mA = mF[end + 1]; int eA = eF[end + 1];   // state end-1
        float mB = mF[end + 2]; int eB = eF[end + 2];   // state end
        const double LN2 = 0.6931471805599453;
        double vA = (mA > 0.f) ? log((double)mA) + (double)eA * LN2 : -1e300;
        double vB = (mB > 0.f) ? log((double)mB) + (double)eB * LN2 : -1e300;
        double mx = fmax(vA, vB);
        double res = mx + log(exp(vA - mx) + exp(vB - mx));
        out[b] = (float)(-res);
    }
}

extern "C" void kernel_launch(void* const* d_in, const int* in_sizes, int n_in,
                              void* d_out, int out_size) {
    // Identify inputs by element count for robustness:
    // y_pred: B*T*C = 33554432, y_true: B*U = 25600, label_len: B = 256.
    const float* y_pred = nullptr;
    const int* y_true = nullptr;
    const int* lab_len = nullptr;
    for (int i = 0; i < n_in; ++i) {
        if (in_sizes[i] == kB * kT * kC)      y_pred  = (const float*)d_in[i];
        else if (in_sizes[i] == kB * kU)      y_true  = (const int*)d_in[i];
        else if (in_sizes[i] == kB)           lab_len = (const int*)d_in[i];
    }
    float* out = (float*)d_out;
    (void)out_size;
    ctc_kernel<<<kB, 256>>>(y_pred, y_true, lab_len, out);
}

// round 6
// speedup vs baseline: 1.1423x; 1.1423x over previous
#include <cuda_runtime.h>
#include <cstdint>
#include <math.h>

// CTC batch cost (TF/Keras: blank = last class, lp = log(p + 1e-7)).
// Forward algorithm in extended-range arithmetic (mantissa float + int exponent
// per state). One WARP per batch element: lane L owns the 8 states [8L, 8L+8),
// alpha lives entirely in registers, cross-lane handoff via shfl_up. No block
// barriers. Probability rows streamed per-warp via cp.async ring (8 slots).
// Mantissas renormalized every 4 steps (stay normal: >= 0.5*eps^4 ~ 5e-29).

namespace {
constexpr int kB = 256, kT = 1024, kC = 128, kU = 100;
constexpr int kS = 2 * kU + 1;     // 201
constexpr int kBlank = kC - 1;     // 127
constexpr float kEps = 1e-7f;
constexpr int RING = 8;
constexpr int NCH  = 8;            // states per lane
constexpr int NLANE = (kS + NCH - 1) / NCH;  // 26 lanes carry states
constexpr int ROWP = kC + 4;       // padded row stride (floats); col 128 == 0.0f
constexpr int WPB  = 2;            // warps (batch elements) per CTA
constexpr int E0   = -100000;      // exponent for value == 0
}

__device__ __forceinline__ void cp_async16(void* smem, const void* gmem) {
    unsigned s = (unsigned)__cvta_generic_to_shared(smem);
    asm volatile("cp.async.ca.shared.global [%0], [%1], 16;" :: "r"(s), "l"(gmem));
}
__device__ __forceinline__ void cp_commit() { asm volatile("cp.async.commit_group;"); }
__device__ __forceinline__ void cp_wait6()  { asm volatile("cp.async.wait_group 6;"); }

// m * 2^(e - emax), flushing below ~2^-126 to zero. Exact when e == emax.
// Works for any positive drifted mantissa (and for m == 0).
__device__ __forceinline__ float alignf(float m, int e, int emax) {
    int d = max(e - emax, -254);            // -254<<23 still fits in int32
    int vi = __float_as_int(m) + (d << 23);
    return __int_as_float(max(vi, 0));
}

__global__ __launch_bounds__(WPB * 32)
void ctc_kernel(const float* __restrict__ yp, const int* __restrict__ yt,
                const int* __restrict__ ll, float* __restrict__ out)
{
    __shared__ __align__(16) float prow[WPB][RING][ROWP];
    __shared__ float stm[WPB][NLANE * NCH];
    __shared__ int   ste[WPB][NLANE * NCH];

    const int warp = threadIdx.x >> 5;
    const int lane = threadIdx.x & 31;
    const int b = blockIdx.x * WPB + warp;
    const float* __restrict__ base = yp + (size_t)b * kT * kC;
    float (* __restrict__ rows)[ROWP] = prow[warp];

    // Zero the pad columns (128..131) of every ring slot (never touched by cp.async).
    if (lane < RING) {
        rows[lane][kC] = 0.f; rows[lane][kC + 1] = 0.f;
        rows[lane][kC + 2] = 0.f; rows[lane][kC + 3] = 0.f;
    }

    // Per-state static config. s = 8*lane + j. Even j -> blank, odd j -> label.
    const int s0 = lane * NCH;
    int   qoff[NCH];   // byte offset of this state's class within a row
    float epsj[NCH];   // kEps for valid states, 0 for s >= kS (=> q == 0 forever)
    bool  skipf[NCH];  // odd j only
    float m[NCH]; int e[NCH];

    #pragma unroll
    for (int j = 0; j < NCH; ++j) {
        const int s = s0 + j;
        const bool valid = (s < kS);
        int c = kC;                       // zero-pad column
        skipf[j] = false;
        if (valid) {
            if (j & 1) {
                c = yt[b * kU + (s >> 1)];
                if (s >= 3) skipf[j] = (c != yt[b * kU + (s >> 1) - 1]);
            } else {
                c = kBlank;
            }
        }
        qoff[j] = c * 4;
        epsj[j] = valid ? kEps : 0.f;
        m[j] = 0.f; e[j] = E0;
    }

    // Prologue: rows 0..6, one commit group each (each lane loads its 16B piece).
    #pragma unroll
    for (int r = 0; r < 7; ++r) {
        cp_async16(&rows[r][lane * 4], base + r * kC + lane * 4);
        cp_commit();
    }
    cp_wait6();        // row 0 landed
    __syncwarp();      // visible across the warp (incl. pad zeros)

    // t = 0 init: only states 0 (blank) and 1 (first label) start nonzero.
    {
        const char* rp = (const char*)rows[0];
        #pragma unroll
        for (int j = 0; j < NCH; ++j) {
            float q = *(const float*)(rp + qoff[j]) + epsj[j];
            if (s0 + j <= 1) { m[j] = q; e[j] = 0; }
        }
    }
    cp_async16(&rows[7][lane * 4], base + 7 * kC + lane * 4);
    cp_commit();

    #pragma unroll 1
    for (int t = 1; t < kT; ++t) {
        cp_wait6();        // row t landed
        __syncwarp();      // cross-lane visibility of this row

        const int nr = t + 7;
        if (nr < kT)
            cp_async16(&rows[nr & (RING - 1)][lane * 4], base + (size_t)nr * kC + lane * 4);
        cp_commit();       // uniform group count (empty groups near the tail)

        // Old boundary states from the previous lane (its j = 7 and j = 6).
        float bm1 = __shfl_up_sync(0xffffffffu, m[NCH - 1], 1);
        int   be1 = __shfl_up_sync(0xffffffffu, e[NCH - 1], 1);
        float bm2 = __shfl_up_sync(0xffffffffu, m[NCH - 2], 1);
        int   be2 = __shfl_up_sync(0xffffffffu, e[NCH - 2], 1);
        if (lane == 0) { bm1 = 0.f; be1 = E0; bm2 = 0.f; be2 = E0; }

        const char* rp = (const char*)rows[t & (RING - 1)];
        const bool renorm = ((t & 3) == 0);

        // Descending j: writes m[j] never clobber a still-needed older value.
        #pragma unroll
        for (int j = NCH - 1; j >= 0; --j) {
            const float a0m = m[j];                     const int a0e = e[j];
            const float a1m = (j >= 1) ? m[j - 1] : bm1; const int a1e = (j >= 1) ? e[j - 1] : be1;
            float q = *(const float*)(rp + qoff[j]) + epsj[j];
            float val; int en;
            if (j & 1) {   // label state: 3-term (skip gated via exponent)
                const float a2m = (j >= 2) ? m[j - 2] : bm2;
                const int   a2e = (j >= 2) ? e[j - 2] : be2;
                const int a2ee = skipf[j] ? a2e : E0;
                const int emax = max(a0e, max(a1e, a2ee));
                float sum = alignf(a0m, a0e, emax)
                          + alignf(a1m, a1e, emax)
                          + alignf(a2m, a2ee, emax);
                val = sum * q; en = emax;
            } else {       // blank state: 2-term
                const int emax = max(a0e, a1e);
                float sum = alignf(a0m, a0e, emax) + alignf(a1m, a1e, emax);
                val = sum * q; en = emax;
            }
            if (renorm) {
                int vi = __float_as_int(val);
                en += ((vi >> 23) & 255) - 126;
                vi = (vi & 0x807FFFFF) | (vi ? 0x3F000000 : 0);  // -> [0.5,1) or 0
                val = __int_as_float(vi);
            }
            m[j] = val; e[j] = en;
        }
    }

    // Readout: stage final (m, e), lane 0 combines states 2L-1 and 2L.
    if (lane < NLANE) {
        #pragma unroll
        for (int j = 0; j < NCH; ++j) {
            stm[warp][lane * NCH + j] = m[j];
            ste[warp][lane * NCH + j] = e[j];
        }
    }
    __syncwarp();
    if (lane == 0) {
        const int L = ll[b];
        const int end = 2 * L;                     // in [2, 200]
        const float mA = stm[warp][end - 1]; const int eA = ste[warp][end - 1];
        const float mB = stm[warp][end];     const int eB = ste[warp][end];
        const double LN2 = 0.6931471805599453;
        double vA = (mA > 0.f) ? log((double)mA) + (double)eA * LN2 : -1e300;
        double vB = (mB > 0.f) ? log((double)mB) + (double)eB * LN2 : -1e300;
        double mx = fmax(vA, vB);
        out[b] = (float)(-(mx + log(exp(vA - mx) + exp(vB - mx))));
    }
}

extern "C" void kernel_launch(void* const* d_in, const int* in_sizes, int n_in,
                              void* d_out, int out_size) {
    const float* y_pred = nullptr;
    const int* y_true = nullptr;
    const int* lab_len = nullptr;
    for (int i = 0; i < n_in; ++i) {
        if (in_sizes[i] == kB * kT * kC)      y_pred  = (const float*)d_in[i];
        else if (in_sizes[i] == kB * kU)      y_true  = (const int*)d_in[i];
        else if (in_sizes[i] == kB)           lab_len = (const int*)d_in[i];
    }
    float* out = (float*)d_out;
    (void)out_size;
    ctc_kernel<<<kB / WPB, WPB * 32>>>(y_pred, y_true, lab_len, out);
}

// round 7
// speedup vs baseline: 1.3967x; 1.2226x over previous
#include <cuda_runtime.h>
#include <cstdint>
#include <math.h>

// CTC batch cost (TF/Keras: blank = last class, lp = log(p + 1e-7)).
// Forward algorithm with BLOCK-FROZEN extended-range arithmetic:
// value[s] = m[s] * 2^E[s]. Exponents E are frozen for 4-step blocks and set
// to the max true exponent over the left window [s-8, s]; the cross-state
// alignment factors s1 = 2^(E[s-1]-E[s]), s2 = 2^(E[s-2]-E[s]) are then
// block-constant floats, so the steady-state update is just
//   m[s] <- (m[s] + s1*m[s-1] + s2*m[s-2]) * q        (blanks: no s2 term)
// One WARP per batch element; lane L owns states [8L, 8L+8); alpha in
// registers; 1 shuffle/step. Rows streamed per-warp via cp.async ring.

namespace {
constexpr int kB = 256, kT = 1024, kC = 128, kU = 100;
constexpr int kS = 2 * kU + 1;     // 201
constexpr int kBlank = kC - 1;     // 127
constexpr float kEps = 1e-7f;
constexpr int RING = 8;
constexpr int WPB  = 2;            // warps (batch elements) per CTA
constexpr int NLANE = 26;          // lanes carrying valid states
constexpr int E0   = -(1 << 24);   // initial exponent for empty states
constexpr int EMIN = -(1 << 30);   // lane-0 boundary "minus infinity"
}

__device__ __forceinline__ void cp_async16(void* smem, const void* gmem) {
    unsigned s = (unsigned)__cvta_generic_to_shared(smem);
    asm volatile("cp.async.ca.shared.global [%0], [%1], 16;" :: "r"(s), "l"(gmem));
}
__device__ __forceinline__ void cp_commit() { asm volatile("cp.async.commit_group;"); }
__device__ __forceinline__ void cp_wait6()  { asm volatile("cp.async.wait_group 6;"); }

// 2^d as float, clamped: d <= -127 -> 0, d >= 126 -> 2^126. Pure ALU.
__device__ __forceinline__ float pow2s(int d) {
    d = min(d, 126); d = max(d, -200);
    return __int_as_float(max((127 + d) << 23, 0));
}
// m * 2^d for d <= 0, flushing results below ~2^-126 to zero.
__device__ __forceinline__ float scale_down(float m, int d) {
    d = max(d, -220);
    return __int_as_float(max(__float_as_int(m) + (d << 23), 0));
}

__global__ __launch_bounds__(WPB * 32)
void ctc_kernel(const float* __restrict__ yp, const int* __restrict__ yt,
                const int* __restrict__ ll, float* __restrict__ out)
{
    __shared__ __align__(16) float prow[WPB][RING][kC];
    __shared__ float stm[WPB][NLANE * 8];
    __shared__ int   ste[WPB][NLANE * 8];

    const int warp = threadIdx.x >> 5;
    const int lane = threadIdx.x & 31;
    const int b = blockIdx.x * WPB + warp;
    const float* __restrict__ base = yp + (size_t)b * kT * kC;
    float (* __restrict__ rows)[kC] = prow[warp];

    // Static per-state config. s = 8*lane + j; even j -> blank, odd -> label.
    // Indices clamped so out-of-range lanes (>= NLANE) read valid memory;
    // their values are garbage but information only flows to HIGHER lanes
    // (shfl_up), so valid states are never contaminated.
    const int s0 = lane * 8;
    int qoffL[4]; bool skipg[4];
    #pragma unroll
    for (int jj = 0; jj < 4; ++jj) {
        const int s = s0 + 2 * jj + 1;
        const int idx = min(s >> 1, kU - 1);
        const int c = yt[b * kU + idx];
        qoffL[jj] = c * 4;
        skipg[jj] = (s >= 3) && (c != yt[b * kU + max(idx - 1, 0)]);
    }

    float m[8]; int E[8]; float s1[8]; float s2o[4];
    #pragma unroll
    for (int j = 0; j < 8; ++j) { m[j] = 0.f; E[j] = E0; }

    // Renorm: recompute true exponents, window-max freeze, realign mantissas,
    // rebuild block-constant scales.
    auto renorm = [&]() {
        int et[8];
        #pragma unroll
        for (int j = 0; j < 8; ++j) {
            const int vi = __float_as_int(m[j]);
            const int f = (vi >> 23) & 255;
            et[j] = vi ? (E[j] + f - 126) : (E[j] - 4096);   // zeros decay fast
            m[j] = __int_as_float((vi & 0x807FFFFF) | (vi ? (126 << 23) : 0));
        }
        int pre[8], suf[8];
        pre[0] = et[0];
        #pragma unroll
        for (int j = 1; j < 8; ++j) pre[j] = max(pre[j - 1], et[j]);
        suf[7] = et[7];
        #pragma unroll
        for (int j = 6; j >= 0; --j) suf[j] = max(suf[j + 1], et[j]);

        int En[8];
        #pragma unroll
        for (int j = 0; j < 8; ++j) {
            int ps = __shfl_up_sync(0xffffffffu, suf[j], 1);
            if (lane == 0) ps = EMIN;
            En[j] = max(pre[j], ps);          // window max over states [s-8, s]
        }
        int pE7 = __shfl_up_sync(0xffffffffu, En[7], 1);
        if (lane == 0) pE7 = EMIN;

        #pragma unroll
        for (int j = 0; j < 8; ++j) m[j] = scale_down(m[j], et[j] - En[j]);

        s1[0] = (lane == 0) ? 0.f : pow2s(pE7 - En[0]);
        #pragma unroll
        for (int j = 1; j < 8; ++j) s1[j] = pow2s(En[j - 1] - En[j]);
        s2o[0] = skipg[0] ? pow2s(pE7   - En[1]) : 0.f;
        s2o[1] = skipg[1] ? pow2s(En[1] - En[3]) : 0.f;
        s2o[2] = skipg[2] ? pow2s(En[3] - En[5]) : 0.f;
        s2o[3] = skipg[3] ? pow2s(En[5] - En[7]) : 0.f;
        #pragma unroll
        for (int j = 0; j < 8; ++j) E[j] = En[j];
    };

    // Prologue: stream rows 0..6, one commit group each.
    #pragma unroll
    for (int r = 0; r < 7; ++r) {
        cp_async16(&rows[r][lane * 4], base + r * kC + lane * 4);
        cp_commit();
    }
    cp_wait6();        // row 0 landed
    __syncwarp();

    // t = 0: only states 0 (blank) and 1 (first label) start nonzero.
    {
        const float* rp = rows[0];
        if (lane == 0) {
            m[0] = rp[kBlank] + kEps;                              E[0] = 0;
            m[1] = *(const float*)((const char*)rp + qoffL[0]) + kEps; E[1] = 0;
        }
    }
    renorm();
    cp_async16(&rows[7][lane * 4], base + 7 * kC + lane * 4);
    cp_commit();

    #pragma unroll 1
    for (int t = 1; t < kT; ++t) {
        cp_wait6();        // row t landed
        __syncwarp();

        const int nr = t + 7;
        if (nr < kT)
            cp_async16(&rows[nr & (RING - 1)][lane * 4], base + (size_t)nr * kC + lane * 4);
        cp_commit();       // uniform group count

        float bm1 = __shfl_up_sync(0xffffffffu, m[7], 1);  // prev lane's state s0-1
        // lane 0: s1[0] == 0 and s2o[0] == 0 kill bm1's (garbage) contribution.

        const char* rp = (const char*)rows[t & (RING - 1)];
        const float qb = *(const float*)(rp + kBlank * 4) + kEps;
        const float q1 = *(const float*)(rp + qoffL[0]) + kEps;
        const float q3 = *(const float*)(rp + qoffL[1]) + kEps;
        const float q5 = *(const float*)(rp + qoffL[2]) + kEps;
        const float q7 = *(const float*)(rp + qoffL[3]) + kEps;

        const float v7 = fmaf(s2o[3], m[5], fmaf(s1[7], m[6], m[7])) * q7;
        const float v6 = fmaf(s1[6], m[5], m[6]) * qb;
        const float v5 = fmaf(s2o[2], m[3], fmaf(s1[5], m[4], m[5])) * q5;
        const float v4 = fmaf(s1[4], m[3], m[4]) * qb;
        const float v3 = fmaf(s2o[1], m[1], fmaf(s1[3], m[2], m[3])) * q3;
        const float v2 = fmaf(s1[2], m[1], m[2]) * qb;
        const float v1 = fmaf(s2o[0], bm1, fmaf(s1[1], m[0], m[1])) * q1;
        const float v0 = fmaf(s1[0], bm1, m[0]) * qb;
        m[0] = v0; m[1] = v1; m[2] = v2; m[3] = v3;
        m[4] = v4; m[5] = v5; m[6] = v6; m[7] = v7;

        if ((t & 3) == 0) renorm();
    }

    // Readout: stage final (m, E); lane 0 combines states 2L-1 and 2L.
    if (lane < NLANE) {
        #pragma unroll
        for (int j = 0; j < 8; ++j) {
            stm[warp][lane * 8 + j] = m[j];
            ste[warp][lane * 8 + j] = E[j];
        }
    }
    __syncwarp();
    if (lane == 0) {
        const int L = ll[b];
        const int end = 2 * L;                         // in [2, 200]
        const float mA = stm[warp][end - 1]; const int eA = ste[warp][end - 1];
        const float mB = stm[warp][end];     const int eB = ste[warp][end];
        const double LN2 = 0.6931471805599453;
        double vA = (mA > 0.f) ? log((double)mA) + (double)eA * LN2 : -1e300;
        double vB = (mB > 0.f) ? log((double)mB) + (double)eB * LN2 : -1e300;
        double mx = fmax(vA, vB);
        out[b] = (float)(-(mx + log(exp(vA - mx) + exp(vB - mx))));
    }
}

extern "C" void kernel_launch(void* const* d_in, const int* in_sizes, int n_in,
                              void* d_out, int out_size) {
    const float* y_pred = nullptr;
    const int* y_true = nullptr;
    const int* lab_len = nullptr;
    for (int i = 0; i < n_in; ++i) {
        if (in_sizes[i] == kB * kT * kC)      y_pred  = (const float*)d_in[i];
        else if (in_sizes[i] == kB * kU)      y_true  = (const int*)d_in[i];
        else if (in_sizes[i] == kB)           lab_len = (const int*)d_in[i];
    }
    float* out = (float*)d_out;
    (void)out_size;
    ctc_kernel<<<kB / WPB, WPB * 32>>>(y_pred, y_true, lab_len, out);
}

// round 10
// speedup vs baseline: 2.0592x; 1.4744x over previous
#include <cuda_runtime.h>
#include <cstdint>
#include <math.h>

// CTC batch cost (TF/Keras: blank = last class, lp = log(p + 1e-7)).
// Forward algorithm with BLOCK-FROZEN extended-range arithmetic (the proven
// R7 numerics): value[s] = m[s] * 2^E[s]. Per-state exponents E are frozen
// for 4-step blocks at the max true exponent over the left window [s-8, s];
// cross-state alignment factors s1 = 2^(E[s-1]-E[s]), s2 = 2^(E[s-2]-E[s])
// are block-constant (clamped pow2 -> alignment only ever scales DOWN or
// mildly up, never overflows). Steady update:
//   m[s] <- (m[s] + s1*m[s-1] + s2*m[s-2]) * q       (blanks: no s2 term)
// One WARP per batch element; lane L owns states [8L, 8L+8); alpha in
// registers; 1 shuffle per steady step. NEW in this round (mechanical only):
// rows streamed in 4-row cp.async groups through a 3-slot ring, block loop
// unrolled x3 so every shared address is [reg + immediate]; q loads through
// hoisted per-class base pointers; renorm hidden between commit and wait.

namespace {
constexpr int kB = 256, kT = 1024, kC = 128, kU = 100;
constexpr int kBlank = kC - 1;     // 127
constexpr float kEps = 1e-7f;
constexpr int WPB  = 2;            // warps (batch elements) per CTA
constexpr int NLANE = 26;          // lanes carrying valid states
constexpr int E0   = -(1 << 24);   // initial exponent for empty states
constexpr int EMIN = -(1 << 30);   // lane-0 boundary "minus infinity"
}

__device__ __forceinline__ void cp_async16(void* smem, const void* gmem) {
    unsigned s = (unsigned)__cvta_generic_to_shared(smem);
    asm volatile("cp.async.ca.shared.global [%0], [%1], 16;" :: "r"(s), "l"(gmem));
}
__device__ __forceinline__ void cp_commit() { asm volatile("cp.async.commit_group;"); }
__device__ __forceinline__ void cp_wait2()  { asm volatile("cp.async.wait_group 2;"); }

// 2^d as float, clamped: d <= -127 -> 0, d >= 126 -> 2^126. Pure ALU.
__device__ __forceinline__ float pow2s(int d) {
    d = min(d, 126); d = max(d, -200);
    return __int_as_float(max((127 + d) << 23, 0));
}
// m * 2^d for d <= 0, flushing results below ~2^-126 to zero.
__device__ __forceinline__ float scale_down(float m, int d) {
    d = max(d, -220);
    return __int_as_float(max(__float_as_int(m) + (d << 23), 0));
}

__global__ __launch_bounds__(WPB * 32)
void ctc_kernel(const float* __restrict__ yp, const int* __restrict__ yt,
                const int* __restrict__ ll, float* __restrict__ out)
{
    __shared__ __align__(16) float prow[WPB][12][kC];   // 3 slots x 4 rows
    __shared__ float stm[WPB][NLANE * 8];
    __shared__ int   ste[WPB][NLANE * 8];

    const int warp = threadIdx.x >> 5;
    const int lane = threadIdx.x & 31;
    const int b = blockIdx.x * WPB + warp;
    const float* __restrict__ base = yp + (size_t)b * kT * kC;

    float* const rowf = &prow[warp][0][0];
    char*  const rbw  = (char*)rowf;

    // ---- static per-lane config (verbatim R7) ------------------------
    // s = 8*lane + j; even j -> blank, odd -> label. Indices clamped so
    // out-of-range lanes read valid memory; their garbage flows only to
    // HIGHER lanes (shfl_up), never contaminating valid states.
    const int s0 = lane * 8;
    int cls[4]; bool skipg[4];
    #pragma unroll
    for (int jj = 0; jj < 4; ++jj) {
        const int s = s0 + 2 * jj + 1;
        const int idx = min(s >> 1, kU - 1);
        const int c = yt[b * kU + idx];
        cls[jj] = c;
        skipg[jj] = (s >= 3) && (c != yt[b * kU + max(idx - 1, 0)]);
    }

    // hoisted q base pointers (row 0 of slot 0); step offsets are immediates
    const float* const qpB = rowf + kBlank;
    const float* const qp1 = rowf + cls[0];
    const float* const qp3 = rowf + cls[1];
    const float* const qp5 = rowf + cls[2];
    const float* const qp7 = rowf + cls[3];

    float m[8]; int E[8]; float s1[8]; float s2o[4];
    #pragma unroll
    for (int j = 0; j < 8; ++j) { m[j] = 0.f; E[j] = E0; }

    // Renorm (verbatim R7): recompute true exponents, window-max freeze,
    // realign mantissas, rebuild block-constant scales.
    auto renorm = [&]() {
        int et[8];
        #pragma unroll
        for (int j = 0; j < 8; ++j) {
            const int vi = __float_as_int(m[j]);
            const int f = (vi >> 23) & 255;
            et[j] = vi ? (E[j] + f - 126) : (E[j] - 4096);   // zeros decay fast
            m[j] = __int_as_float((vi & 0x807FFFFF) | (vi ? (126 << 23) : 0));
        }
        int pre[8], suf[8];
        pre[0] = et[0];
        #pragma unroll
        for (int j = 1; j < 8; ++j) pre[j] = max(pre[j - 1], et[j]);
        suf[7] = et[7];
        #pragma unroll
        for (int j = 6; j >= 0; --j) suf[j] = max(suf[j + 1], et[j]);

        int En[8];
        #pragma unroll
        for (int j = 0; j < 8; ++j) {
            int ps = __shfl_up_sync(0xffffffffu, suf[j], 1);
            if (lane == 0) ps = EMIN;
            En[j] = max(pre[j], ps);          // window max over states [s-8, s]
        }
        int pE7 = __shfl_up_sync(0xffffffffu, En[7], 1);
        if (lane == 0) pE7 = EMIN;

        #pragma unroll
        for (int j = 0; j < 8; ++j) m[j] = scale_down(m[j], et[j] - En[j]);

        s1[0] = (lane == 0) ? 0.f : pow2s(pE7 - En[0]);
        #pragma unroll
        for (int j = 1; j < 8; ++j) s1[j] = pow2s(En[j - 1] - En[j]);
        s2o[0] = skipg[0] ? pow2s(pE7   - En[1]) : 0.f;
        s2o[1] = skipg[1] ? pow2s(En[1] - En[3]) : 0.f;
        s2o[2] = skipg[2] ? pow2s(En[3] - En[5]) : 0.f;
        s2o[3] = skipg[3] ? pow2s(En[5] - En[7]) : 0.f;
        #pragma unroll
        for (int j = 0; j < 8; ++j) E[j] = En[j];
    };

#define STEP(OFF) do {                                                        \
    float bm1 = __shfl_up_sync(0xffffffffu, m[7], 1);                         \
    float qb = qpB[(OFF) >> 2] + kEps;                                        \
    float q1 = qp1[(OFF) >> 2] + kEps;                                        \
    float q3 = qp3[(OFF) >> 2] + kEps;                                        \
    float q5 = qp5[(OFF) >> 2] + kEps;                                        \
    float q7 = qp7[(OFF) >> 2] + kEps;                                        \
    float v7 = fmaf(s2o[3], m[5], fmaf(s1[7], m[6], m[7])) * q7;              \
    float v6 = fmaf(s1[6], m[5], m[6]) * qb;                                  \
    float v5 = fmaf(s2o[2], m[3], fmaf(s1[5], m[4], m[5])) * q5;              \
    float v4 = fmaf(s1[4], m[3], m[4]) * qb;                                  \
    float v3 = fmaf(s2o[1], m[1], fmaf(s1[3], m[2], m[3])) * q3;              \
    float v2 = fmaf(s1[2], m[1], m[2]) * qb;                                  \
    float v1 = fmaf(s2o[0], bm1, fmaf(s1[1], m[0], m[1])) * q1;               \
    float v0 = fmaf(s1[0], bm1, m[0]) * qb;                                   \
    m[0] = v0; m[1] = v1; m[2] = v2; m[3] = v3;                               \
    m[4] = v4; m[5] = v5; m[6] = v6; m[7] = v7;                               \
} while (0)

// One 4-step block: prefetch next group into slot PS, renorm (covers the 4
// steps just finished; gap between renorms stays <= 4 as in R7), wait, run
// 4 steps on slot CS.
#define BLOCK(CS, PS, ISSUE) do {                                             \
    if (ISSUE) {                                                              \
        cp_async16(rbw + (PS) * 2048 +    0 + lane * 16, gp +    0);          \
        cp_async16(rbw + (PS) * 2048 +  512 + lane * 16, gp +  512);          \
        cp_async16(rbw + (PS) * 2048 + 1024 + lane * 16, gp + 1024);          \
        cp_async16(rbw + (PS) * 2048 + 1536 + lane * 16, gp + 1536);          \
    }                                                                         \
    cp_commit();                                                              \
    gp += 2048;                                                               \
    renorm();                                                                 \
    cp_wait2();                                                               \
    __syncwarp();                                                             \
    STEP((CS) * 2048 +    0);                                                 \
    STEP((CS) * 2048 +  512);                                                 \
    STEP((CS) * 2048 + 1024);                                                 \
    STEP((CS) * 2048 + 1536);                                                 \
} while (0)

    // ---- prologue: groups 0..2 (rows 0..11) --------------------------
    const char* gp = (const char*)base + lane * 16;
    #pragma unroll
    for (int g = 0; g < 3; ++g) {
        #pragma unroll
        for (int r = 0; r < 4; ++r)
            cp_async16(rbw + g * 2048 + r * 512 + lane * 16,
                       gp + g * 2048 + r * 512);
        cp_commit();
    }
    gp += 3 * 2048;
    cp_wait2();        // group 0 landed
    __syncwarp();

    // t = 0: only states 0 (blank) and 1 (first label) start nonzero.
    if (lane == 0) {
        m[0] = qpB[0] + kEps;  E[0] = 0;
        m[1] = qp1[0] + kEps;  E[1] = 0;
    }
    renorm();          // set up s1/s2o for steps 1..3 (as in R7)
    // steps t = 1..3 (rows 1..3, slot 0)
    STEP(512); STEP(1024); STEP(1536);

    // ---- main: blocks k = 1..252, unrolled x3 ------------------------
    #pragma unroll 1
    for (int kk = 0; kk < 84; ++kk) {
        BLOCK(1, 0, true);
        BLOCK(2, 1, true);
        BLOCK(0, 2, true);
    }
    // peel k = 253 (issues last group 255), 254, 255 (empty commits)
    BLOCK(1, 0, true);
    BLOCK(2, 1, false);
    BLOCK(0, 2, false);

#undef BLOCK
#undef STEP

    // ---- readout (verbatim R7) ----------------------------------------
    if (lane < NLANE) {
        #pragma unroll
        for (int j = 0; j < 8; ++j) {
            stm[warp][lane * 8 + j] = m[j];
            ste[warp][lane * 8 + j] = E[j];
        }
    }
    __syncwarp();
    if (lane == 0) {
        const int L = ll[b];
        const int end = 2 * L;                       // in [2, 200]
        const float mA = stm[warp][end - 1]; const int eA = ste[warp][end - 1];
        const float mB = stm[warp][end];     const int eB = ste[warp][end];
        const double LN2 = 0.6931471805599453;
        double vA = (mA > 0.f) ? log((double)mA) + (double)eA * LN2 : -1e300;
        double vB = (mB > 0.f) ? log((double)mB) + (double)eB * LN2 : -1e300;
        double mx = fmax(vA, vB);
        out[b] = (float)(-(mx + log(exp(vA - mx) + exp(vB - mx))));
    }
}

extern "C" void kernel_launch(void* const* d_in, const int* in_sizes, int n_in,
                              void* d_out, int out_size) {
    const float* y_pred = nullptr;
    const int* y_true = nullptr;
    const int* lab_len = nullptr;
    for (int i = 0; i < n_in; ++i) {
        if (in_sizes[i] == kB * kT * kC)      y_pred  = (const float*)d_in[i];
        else if (in_sizes[i] == kB * kU)      y_true  = (const int*)d_in[i];
        else if (in_sizes[i] == kB)           lab_len = (const int*)d_in[i];
    }
    float* out = (float*)d_out;
    (void)out_size;
    ctc_kernel<<<kB / WPB, WPB * 32>>>(y_pred, y_true, lab_len, out);
}